// round 3
// baseline (speedup 1.0000x reference)
#include <cuda_runtime.h>
#include <math.h>

#define FIELD 39
#define EMBD 8
#define MAXB 16384
#define D0 312
#define D1 512
#define D2 256
#define D3 128

// Scratch (allocation-free rule: __device__ globals)
__device__ float g_S[FIELD * FIELD];
__device__ float g_li[MAXB];
__device__ float g_h0[MAXB * D0];
__device__ float g_h1[MAXB * D1];
__device__ float g_h2[MAXB * D2];
__device__ float g_h3[MAXB * D3];

// ---------------------------------------------------------------------------
// 1. S matrix: constant 39x39, strictly upper triangular.
//    Vi[i][g][e] = FM_V[i, i*1000, g, e];  S[i][j] = sum_e Vi[i][j%8][e]*Vi[j][i%8][e]
// ---------------------------------------------------------------------------
__global__ void compute_S_kernel(const float* __restrict__ FM_V) {
    __shared__ float Vi[FIELD][8][EMBD];
    for (int idx = threadIdx.x; idx < FIELD * 64; idx += blockDim.x) {
        int i = idx / 64;
        int r = idx % 64;
        // offset = ((i*50000 + i*1000) * 8 + g) * 8 + e = i*51000*64 + r
        long long off = (long long)i * (51000LL * 64LL) + r;
        Vi[i][r >> 3][r & 7] = FM_V[off];
    }
    __syncthreads();
    for (int idx = threadIdx.x; idx < FIELD * FIELD; idx += blockDim.x) {
        int i = idx / FIELD, j = idx % FIELD;
        float s = 0.f;
        if (j > i) {
#pragma unroll
            for (int e = 0; e < EMBD; e++)
                s += Vi[i][j & 7][e] * Vi[j][i & 7][e];
        }
        g_S[idx] = s;
    }
}

// ---------------------------------------------------------------------------
// 2. linear + interaction per sample (one thread per sample)
// ---------------------------------------------------------------------------
__global__ __launch_bounds__(256) void linear_inter_kernel(
    const int* __restrict__ ids, const float* __restrict__ vals,
    const float* __restrict__ FM_W, const float* __restrict__ FM_B, int B)
{
    __shared__ float Ss[FIELD * FIELD];
    for (int idx = threadIdx.x; idx < FIELD * FIELD; idx += blockDim.x)
        Ss[idx] = g_S[idx];
    __syncthreads();

    int b = blockIdx.x * blockDim.x + threadIdx.x;
    if (b >= B) return;

    float v[FIELD];
    float lin = 0.f;
#pragma unroll
    for (int f = 0; f < FIELD; f++) {
        v[f] = vals[b * FIELD + f];
        lin += FM_W[ids[b * FIELD + f]] * v[f];
    }
    float inter = 0.f;
#pragma unroll
    for (int i = 0; i < FIELD; i++) {
        float ti = 0.f;
#pragma unroll
        for (int j = i + 1; j < FIELD; j++)
            ti += Ss[i * FIELD + j] * v[j];
        inter += v[i] * ti;
    }
    g_li[b] = lin + inter + FM_B[0];
}

// ---------------------------------------------------------------------------
// 3. embedding gather -> h0 (B x 312), thread per (b, field), float4 x2
// ---------------------------------------------------------------------------
__global__ void gather_kernel(const int* __restrict__ ids,
                              const float* __restrict__ emb, int B)
{
    int idx = blockIdx.x * blockDim.x + threadIdx.x;
    if (idx >= B * FIELD) return;
    int id = ids[idx];
    int b = idx / FIELD, f = idx % FIELD;
    const float4* e = (const float4*)(emb + (size_t)id * EMBD);
    float4* dst = (float4*)(g_h0 + (size_t)b * D0 + f * EMBD);
    float4 e0 = e[0];
    float4 e1 = e[1];
    dst[0] = e0;
    dst[1] = e1;
}

// ---------------------------------------------------------------------------
// 4. fp32 SGEMM + bias + ReLU.  C[M,N] = relu(A[M,K] @ W[K,N] + bias)
//    BM=BN=128, BK=8, 256 threads, 8x8 per-thread tile.
//    Requires M%128==0, N%128==0, K%8==0 (true for all layers).
// ---------------------------------------------------------------------------
__global__ __launch_bounds__(256) void gemm128_bias_relu(
    const float* __restrict__ A, const float* __restrict__ W,
    const float* __restrict__ bias, float* __restrict__ C,
    int M, int N, int K)
{
    __shared__ float As[8][128];
    __shared__ float Bs[8][128];

    const int t = threadIdx.x;
    const int bm = blockIdx.y * 128;
    const int bn = blockIdx.x * 128;
    const int tx = t & 15, ty = t >> 4;
    const int tm = ty * 8, tn = tx * 8;

    // load mappings (one float4 each per stage)
    const int arow = t >> 1, acol = (t & 1) * 4;   // A: 128 rows x 8 cols
    const int wrow = t >> 5, wcol = (t & 31) * 4;  // W: 8 rows x 128 cols

    float acc[8][8] = {};

    const float* Ap = A + (size_t)(bm + arow) * K + acol;
    for (int k0 = 0; k0 < K; k0 += 8) {
        float4 a = *(const float4*)(Ap + k0);
        As[acol + 0][arow] = a.x;
        As[acol + 1][arow] = a.y;
        As[acol + 2][arow] = a.z;
        As[acol + 3][arow] = a.w;
        float4 w = *(const float4*)(W + (size_t)(k0 + wrow) * N + bn + wcol);
        *(float4*)&Bs[wrow][wcol] = w;
        __syncthreads();

#pragma unroll
        for (int k = 0; k < 8; k++) {
            float ra[8], rb[8];
            *(float4*)&ra[0] = *(const float4*)&As[k][tm];
            *(float4*)&ra[4] = *(const float4*)&As[k][tm + 4];
            *(float4*)&rb[0] = *(const float4*)&Bs[k][tn];
            *(float4*)&rb[4] = *(const float4*)&Bs[k][tn + 4];
#pragma unroll
            for (int i = 0; i < 8; i++)
#pragma unroll
                for (int j = 0; j < 8; j++)
                    acc[i][j] += ra[i] * rb[j];
        }
        __syncthreads();
    }

    float bvals[8];
#pragma unroll
    for (int j = 0; j < 8; j++) bvals[j] = bias[bn + tn + j];

#pragma unroll
    for (int i = 0; i < 8; i++) {
        float* crow = C + (size_t)(bm + tm + i) * N + bn + tn;
#pragma unroll
        for (int j = 0; j < 8; j += 4) {
            float4 o;
            o.x = fmaxf(acc[i][j + 0] + bvals[j + 0], 0.f);
            o.y = fmaxf(acc[i][j + 1] + bvals[j + 1], 0.f);
            o.z = fmaxf(acc[i][j + 2] + bvals[j + 2], 0.f);
            o.w = fmaxf(acc[i][j + 3] + bvals[j + 3], 0.f);
            *(float4*)(crow + j) = o;
        }
    }
}

// ---------------------------------------------------------------------------
// 5. output head: warp per sample. dot(h3, outW) + outB + li -> sigmoid
// ---------------------------------------------------------------------------
__global__ __launch_bounds__(256) void out_kernel(
    const float* __restrict__ outW, const float* __restrict__ outB,
    float* __restrict__ out, int B)
{
    int warp = (blockIdx.x * blockDim.x + threadIdx.x) >> 5;
    int lane = threadIdx.x & 31;
    if (warp >= B) return;
    const float* h = g_h3 + (size_t)warp * D3;
    float s = 0.f;
#pragma unroll
    for (int j = 0; j < D3 / 32; j++)
        s += h[lane + 32 * j] * outW[lane + 32 * j];
#pragma unroll
    for (int o = 16; o; o >>= 1)
        s += __shfl_down_sync(0xffffffffu, s, o);
    if (lane == 0) {
        float x = s + outB[0] + g_li[warp];
        out[warp] = 1.f / (1.f + expf(-x));
    }
}

// ---------------------------------------------------------------------------
extern "C" void kernel_launch(void* const* d_in, const int* in_sizes, int n_in,
                              void* d_out, int out_size)
{
    const int*   feat_ids  = (const int*)  d_in[0];
    const float* feat_vals = (const float*)d_in[1];
    const float* FM_W      = (const float*)d_in[2];
    const float* FM_V      = (const float*)d_in[3];
    const float* FM_B      = (const float*)d_in[4];
    const float* emb       = (const float*)d_in[5];
    const float* W0        = (const float*)d_in[6];
    const float* B0        = (const float*)d_in[7];
    const float* W1        = (const float*)d_in[8];
    const float* B1        = (const float*)d_in[9];
    const float* W2        = (const float*)d_in[10];
    const float* B2        = (const float*)d_in[11];
    const float* outW      = (const float*)d_in[12];
    const float* outB      = (const float*)d_in[13];
    float* out = (float*)d_out;

    int B = in_sizes[0] / FIELD;
    if (B > MAXB) B = MAXB;

    float *h0, *h1, *h2, *h3;
    cudaGetSymbolAddress((void**)&h0, g_h0);
    cudaGetSymbolAddress((void**)&h1, g_h1);
    cudaGetSymbolAddress((void**)&h2, g_h2);
    cudaGetSymbolAddress((void**)&h3, g_h3);

    compute_S_kernel<<<1, 256>>>(FM_V);
    linear_inter_kernel<<<(B + 255) / 256, 256>>>(feat_ids, feat_vals, FM_W, FM_B, B);
    gather_kernel<<<(B * FIELD + 255) / 256, 256>>>(feat_ids, emb, B);

    gemm128_bias_relu<<<dim3(D1 / 128, B / 128), 256>>>(h0, W0, B0, h1, B, D1, D0);
    gemm128_bias_relu<<<dim3(D2 / 128, B / 128), 256>>>(h1, W1, B1, h2, B, D2, D1);
    gemm128_bias_relu<<<dim3(D3 / 128, B / 128), 256>>>(h2, W2, B2, h3, B, D3, D2);

    out_kernel<<<(B * 32 + 255) / 256, 256>>>(outW, outB, out, B);
}

// round 4
// speedup vs baseline: 1.9785x; 1.9785x over previous
#include <cuda_runtime.h>
#include <math.h>

#define FIELD 39
#define EMBD 8
#define MAXB 16384
#define D0 312
#define D1 512
#define D2 256
#define D3 128

// Scratch (allocation-free rule: __device__ globals)
__device__ float g_S[FIELD * FIELD];
__device__ float g_li[MAXB];
__device__ float g_h0[MAXB * D0];
__device__ float g_h1[MAXB * D1];
__device__ float g_h2[MAXB * D2];
__device__ float g_h3[MAXB * D3];

// ---------------------------------------------------------------------------
// 1. S matrix: constant 39x39, strictly upper triangular.
// ---------------------------------------------------------------------------
__global__ void compute_S_kernel(const float* __restrict__ FM_V) {
    __shared__ float Vi[FIELD][8][EMBD];
    for (int idx = threadIdx.x; idx < FIELD * 64; idx += blockDim.x) {
        int i = idx / 64;
        int r = idx % 64;
        long long off = (long long)i * (51000LL * 64LL) + r;
        Vi[i][r >> 3][r & 7] = FM_V[off];
    }
    __syncthreads();
    for (int idx = threadIdx.x; idx < FIELD * FIELD; idx += blockDim.x) {
        int i = idx / FIELD, j = idx % FIELD;
        float s = 0.f;
        if (j > i) {
#pragma unroll
            for (int e = 0; e < EMBD; e++)
                s += Vi[i][j & 7][e] * Vi[j][i & 7][e];
        }
        g_S[idx] = s;
    }
}

// ---------------------------------------------------------------------------
// 2. linear + interaction per sample (one thread per sample)
// ---------------------------------------------------------------------------
__global__ __launch_bounds__(256) void linear_inter_kernel(
    const int* __restrict__ ids, const float* __restrict__ vals,
    const float* __restrict__ FM_W, const float* __restrict__ FM_B, int B)
{
    __shared__ float Ss[FIELD * FIELD];
    for (int idx = threadIdx.x; idx < FIELD * FIELD; idx += blockDim.x)
        Ss[idx] = g_S[idx];
    __syncthreads();

    int b = blockIdx.x * blockDim.x + threadIdx.x;
    if (b >= B) return;

    float v[FIELD];
    float lin = 0.f;
#pragma unroll
    for (int f = 0; f < FIELD; f++) {
        v[f] = vals[b * FIELD + f];
        lin += FM_W[ids[b * FIELD + f]] * v[f];
    }
    float inter = 0.f;
#pragma unroll
    for (int i = 0; i < FIELD; i++) {
        float ti = 0.f;
#pragma unroll
        for (int j = i + 1; j < FIELD; j++)
            ti += Ss[i * FIELD + j] * v[j];
        inter += v[i] * ti;
    }
    g_li[b] = lin + inter + FM_B[0];
}

// ---------------------------------------------------------------------------
// 3. embedding gather -> h0 (B x 312)
// ---------------------------------------------------------------------------
__global__ void gather_kernel(const int* __restrict__ ids,
                              const float* __restrict__ emb, int B)
{
    int idx = blockIdx.x * blockDim.x + threadIdx.x;
    if (idx >= B * FIELD) return;
    int id = ids[idx];
    int b = idx / FIELD, f = idx % FIELD;
    const float4* e = (const float4*)(emb + (size_t)id * EMBD);
    float4* dst = (float4*)(g_h0 + (size_t)b * D0 + f * EMBD);
    float4 e0 = e[0];
    float4 e1 = e[1];
    dst[0] = e0;
    dst[1] = e1;
}

// ---------------------------------------------------------------------------
// 4. tf32 tensor-core GEMM + bias + ReLU.
//    C[M,N] = relu(A[M,K] @ W[K,N] + bias)
//    BM=BN=128, BK=8, 256 threads (8 warps, 2x4), warp tile 64x32.
//    mma.sync.m16n8k8.tf32, fp32 accumulate. Double-buffered smem, pad=136.
//    Requires M%128==0, N%128==0, K%8==0.
// ---------------------------------------------------------------------------
#define PAD 136

__device__ __forceinline__ float to_tf32(float x) {
    float r;
    asm("cvt.rna.tf32.f32 %0, %1;" : "=f"(r) : "f"(x));
    return r;
}

__device__ __forceinline__ void mma_tf32(float* c, const unsigned* a, const unsigned* b) {
    asm volatile(
        "mma.sync.aligned.m16n8k8.row.col.f32.tf32.tf32.f32 "
        "{%0,%1,%2,%3}, {%4,%5,%6,%7}, {%8,%9}, {%0,%1,%2,%3};"
        : "+f"(c[0]), "+f"(c[1]), "+f"(c[2]), "+f"(c[3])
        : "r"(a[0]), "r"(a[1]), "r"(a[2]), "r"(a[3]), "r"(b[0]), "r"(b[1]));
}

__global__ __launch_bounds__(256, 2) void gemm_tf32_bias_relu(
    const float* __restrict__ A, const float* __restrict__ W,
    const float* __restrict__ bias, float* __restrict__ C,
    int M, int N, int K)
{
    __shared__ float As[2][8][PAD];  // [k][m], padded
    __shared__ float Bs[2][8][PAD];  // [k][n], padded

    const int t = threadIdx.x;
    const int lane = t & 31;
    const int warp = t >> 5;
    const int wm = (warp >> 2) * 64;   // warp M offset within block
    const int wn = (warp & 3) * 32;    // warp N offset within block
    const int bm = blockIdx.y * 128;
    const int bn = blockIdx.x * 128;

    // global load mapping
    const int am = t >> 1, ak = (t & 1) * 4;     // A: float4 along K
    const int bk = t >> 5, bn4 = (t & 31) * 4;   // W: float4 along N

    const float* Ag = A + (size_t)(bm + am) * K + ak;
    const float* Wg = W + (size_t)bk * N + bn + bn4;

    float acc[4][4][4] = {};  // [mt][nt][reg]

    // prefetch stage 0
    float4 ra = *(const float4*)Ag;
    float4 rw = *(const float4*)Wg;
    As[0][ak + 0][am] = to_tf32(ra.x);
    As[0][ak + 1][am] = to_tf32(ra.y);
    As[0][ak + 2][am] = to_tf32(ra.z);
    As[0][ak + 3][am] = to_tf32(ra.w);
    {
        float4 cw = make_float4(to_tf32(rw.x), to_tf32(rw.y), to_tf32(rw.z), to_tf32(rw.w));
        *(float4*)&Bs[0][bk][bn4] = cw;
    }
    __syncthreads();

    const int nk = K >> 3;
    const int r = lane >> 2, c = lane & 3;

    for (int k0 = 0; k0 < nk; k0++) {
        const int cur = k0 & 1;
        const bool more = (k0 + 1 < nk);
        if (more) {
            ra = *(const float4*)(Ag + (k0 + 1) * 8);
            rw = *(const float4*)(Wg + (size_t)(k0 + 1) * 8 * N);
        }

        // load fragments
        unsigned a[4][4], b[4][2];
#pragma unroll
        for (int mt = 0; mt < 4; mt++) {
            int m = wm + mt * 16 + r;
            a[mt][0] = __float_as_uint(As[cur][c][m]);
            a[mt][1] = __float_as_uint(As[cur][c][m + 8]);
            a[mt][2] = __float_as_uint(As[cur][c + 4][m]);
            a[mt][3] = __float_as_uint(As[cur][c + 4][m + 8]);
        }
#pragma unroll
        for (int nt = 0; nt < 4; nt++) {
            int n = wn + nt * 8 + r;
            b[nt][0] = __float_as_uint(Bs[cur][c][n]);
            b[nt][1] = __float_as_uint(Bs[cur][c + 4][n]);
        }
#pragma unroll
        for (int mt = 0; mt < 4; mt++)
#pragma unroll
            for (int nt = 0; nt < 4; nt++)
                mma_tf32(acc[mt][nt], a[mt], b[nt]);

        if (more) {
            const int nxt = cur ^ 1;
            As[nxt][ak + 0][am] = to_tf32(ra.x);
            As[nxt][ak + 1][am] = to_tf32(ra.y);
            As[nxt][ak + 2][am] = to_tf32(ra.z);
            As[nxt][ak + 3][am] = to_tf32(ra.w);
            float4 cw = make_float4(to_tf32(rw.x), to_tf32(rw.y), to_tf32(rw.z), to_tf32(rw.w));
            *(float4*)&Bs[nxt][bk][bn4] = cw;
        }
        __syncthreads();
    }

    // epilogue: bias + relu, float2 stores
#pragma unroll
    for (int nt = 0; nt < 4; nt++) {
        int col = bn + wn + nt * 8 + 2 * (lane & 3);
        float b0 = bias[col], b1 = bias[col + 1];
#pragma unroll
        for (int mt = 0; mt < 4; mt++) {
            int row0 = bm + wm + mt * 16 + (lane >> 2);
            float2 o0, o1;
            o0.x = fmaxf(acc[mt][nt][0] + b0, 0.f);
            o0.y = fmaxf(acc[mt][nt][1] + b1, 0.f);
            o1.x = fmaxf(acc[mt][nt][2] + b0, 0.f);
            o1.y = fmaxf(acc[mt][nt][3] + b1, 0.f);
            *(float2*)(C + (size_t)row0 * N + col) = o0;
            *(float2*)(C + (size_t)(row0 + 8) * N + col) = o1;
        }
    }
}

// ---------------------------------------------------------------------------
// 5. output head: warp per sample. dot(h3, outW) + outB + li -> sigmoid
// ---------------------------------------------------------------------------
__global__ __launch_bounds__(256) void out_kernel(
    const float* __restrict__ outW, const float* __restrict__ outB,
    float* __restrict__ out, int B)
{
    int warp = (blockIdx.x * blockDim.x + threadIdx.x) >> 5;
    int lane = threadIdx.x & 31;
    if (warp >= B) return;
    const float* h = g_h3 + (size_t)warp * D3;
    float s = 0.f;
#pragma unroll
    for (int j = 0; j < D3 / 32; j++)
        s += h[lane + 32 * j] * outW[lane + 32 * j];
#pragma unroll
    for (int o = 16; o; o >>= 1)
        s += __shfl_down_sync(0xffffffffu, s, o);
    if (lane == 0) {
        float x = s + outB[0] + g_li[warp];
        out[warp] = 1.f / (1.f + expf(-x));
    }
}

// ---------------------------------------------------------------------------
extern "C" void kernel_launch(void* const* d_in, const int* in_sizes, int n_in,
                              void* d_out, int out_size)
{
    const int*   feat_ids  = (const int*)  d_in[0];
    const float* feat_vals = (const float*)d_in[1];
    const float* FM_W      = (const float*)d_in[2];
    const float* FM_V      = (const float*)d_in[3];
    const float* FM_B      = (const float*)d_in[4];
    const float* emb       = (const float*)d_in[5];
    const float* W0        = (const float*)d_in[6];
    const float* B0        = (const float*)d_in[7];
    const float* W1        = (const float*)d_in[8];
    const float* B1        = (const float*)d_in[9];
    const float* W2        = (const float*)d_in[10];
    const float* B2        = (const float*)d_in[11];
    const float* outW      = (const float*)d_in[12];
    const float* outB      = (const float*)d_in[13];
    float* out = (float*)d_out;

    int B = in_sizes[0] / FIELD;
    if (B > MAXB) B = MAXB;

    float *h0, *h1, *h2, *h3;
    cudaGetSymbolAddress((void**)&h0, g_h0);
    cudaGetSymbolAddress((void**)&h1, g_h1);
    cudaGetSymbolAddress((void**)&h2, g_h2);
    cudaGetSymbolAddress((void**)&h3, g_h3);

    compute_S_kernel<<<1, 256>>>(FM_V);
    linear_inter_kernel<<<(B + 255) / 256, 256>>>(feat_ids, feat_vals, FM_W, FM_B, B);
    gather_kernel<<<(B * FIELD + 255) / 256, 256>>>(feat_ids, emb, B);

    gemm_tf32_bias_relu<<<dim3(D1 / 128, B / 128), 256>>>(h0, W0, B0, h1, B, D1, D0);
    gemm_tf32_bias_relu<<<dim3(D2 / 128, B / 128), 256>>>(h1, W1, B1, h2, B, D2, D1);
    gemm_tf32_bias_relu<<<dim3(D3 / 128, B / 128), 256>>>(h2, W2, B2, h3, B, D3, D2);

    out_kernel<<<(B * 32 + 255) / 256, 256>>>(outW, outB, out, B);
}

// round 5
// speedup vs baseline: 3.4399x; 1.7386x over previous
#include <cuda_runtime.h>
#include <cuda_bf16.h>
#include <math.h>

#define FIELD 39
#define EMBD 8
#define MAXB 16384
#define D0 312
#define D0P 320          // padded K for layer 0
#define D1 512
#define D2 256
#define D3 128

#define KW0 (D0P / 2)    // 160 words per h0 row
#define KW1 (D1 / 2)     // 256
#define KW2 (D2 / 2)     // 128
#define NW3 (D3 / 2)     // 64

// Scratch (allocation-free rule: __device__ globals). Activations packed bf16x2.
__device__ float    g_S[FIELD * FIELD];
__device__ float    g_li[MAXB];
__device__ unsigned g_h0[MAXB * KW0];
__device__ unsigned g_h1[MAXB * KW1];
__device__ unsigned g_h2[MAXB * KW2];
__device__ unsigned g_h3[MAXB * NW3];
__device__ unsigned g_w0p[KW0 * D1];   // packed weights [K/2][N]
__device__ unsigned g_w1p[KW1 * D2];
__device__ unsigned g_w2p[KW2 * D3];

__device__ __forceinline__ unsigned pack_bf2(float a, float b) {
    __nv_bfloat162 p = __floats2bfloat162_rn(a, b);
    return *(unsigned*)&p;
}

// ---------------------------------------------------------------------------
// 1. S matrix: constant 39x39, strictly upper triangular.
// ---------------------------------------------------------------------------
__global__ void compute_S_kernel(const float* __restrict__ FM_V) {
    __shared__ float Vi[FIELD][8][EMBD];
    for (int idx = threadIdx.x; idx < FIELD * 64; idx += blockDim.x) {
        int i = idx / 64;
        int r = idx % 64;
        long long off = (long long)i * (51000LL * 64LL) + r;
        Vi[i][r >> 3][r & 7] = FM_V[off];
    }
    __syncthreads();
    for (int idx = threadIdx.x; idx < FIELD * FIELD; idx += blockDim.x) {
        int i = idx / FIELD, j = idx % FIELD;
        float s = 0.f;
        if (j > i) {
#pragma unroll
            for (int e = 0; e < EMBD; e++)
                s += Vi[i][j & 7][e] * Vi[j][i & 7][e];
        }
        g_S[idx] = s;
    }
}

// ---------------------------------------------------------------------------
// 2. linear + interaction per sample (full fp32)
// ---------------------------------------------------------------------------
__global__ __launch_bounds__(256) void linear_inter_kernel(
    const int* __restrict__ ids, const float* __restrict__ vals,
    const float* __restrict__ FM_W, const float* __restrict__ FM_B, int B)
{
    __shared__ float Ss[FIELD * FIELD];
    for (int idx = threadIdx.x; idx < FIELD * FIELD; idx += blockDim.x)
        Ss[idx] = g_S[idx];
    __syncthreads();

    int b = blockIdx.x * blockDim.x + threadIdx.x;
    if (b >= B) return;

    float v[FIELD];
    float lin = 0.f;
#pragma unroll
    for (int f = 0; f < FIELD; f++) {
        v[f] = vals[b * FIELD + f];
        lin += FM_W[ids[b * FIELD + f]] * v[f];
    }
    float inter = 0.f;
#pragma unroll
    for (int i = 0; i < FIELD; i++) {
        float ti = 0.f;
#pragma unroll
        for (int j = i + 1; j < FIELD; j++)
            ti += Ss[i * FIELD + j] * v[j];
        inter += v[i] * ti;
    }
    g_li[b] = lin + inter + FM_B[0];
}

// ---------------------------------------------------------------------------
// 3. embedding gather -> packed bf16 h0 (B x 160 words, last 4 words zero)
//    thread per (b, f) with f in [0, 40); f==39 writes the zero pad.
// ---------------------------------------------------------------------------
__global__ void gather_kernel(const int* __restrict__ ids,
                              const float* __restrict__ emb, int B)
{
    int idx = blockIdx.x * blockDim.x + threadIdx.x;
    if (idx >= B * 40) return;
    int b = idx / 40, f = idx % 40;
    uint4 o;
    if (f < FIELD) {
        int id = ids[b * FIELD + f];
        const float4* e = (const float4*)(emb + (size_t)id * EMBD);
        float4 e0 = e[0];
        float4 e1 = e[1];
        o.x = pack_bf2(e0.x, e0.y);
        o.y = pack_bf2(e0.z, e0.w);
        o.z = pack_bf2(e1.x, e1.y);
        o.w = pack_bf2(e1.z, e1.w);
    } else {
        o = make_uint4(0u, 0u, 0u, 0u);
    }
    *(uint4*)(g_h0 + (size_t)b * KW0 + f * 4) = o;
}

// ---------------------------------------------------------------------------
// 3b. pack fp32 weights [K][N] -> bf16x2 words [KW][N], zero-pad k >= K
// ---------------------------------------------------------------------------
__global__ void pack_w_kernel(const float* __restrict__ W, unsigned* __restrict__ out,
                              int K, int N, int KW)
{
    int idx = blockIdx.x * blockDim.x + threadIdx.x;
    if (idx >= KW * N) return;
    int kp = idx / N, n = idx % N;
    int k0 = 2 * kp;
    float w0 = (k0     < K) ? W[(size_t)k0 * N + n]       : 0.f;
    float w1 = (k0 + 1 < K) ? W[(size_t)(k0 + 1) * N + n] : 0.f;
    out[idx] = pack_bf2(w0, w1);
}

// ---------------------------------------------------------------------------
// 4. bf16 tensor-core GEMM + bias + ReLU, packed-pair layout.
//    C(packed)[M][N/2] = relu(A(packed)[M][KW] @ Wp[KW][N] + bias)
//    BM=BN=128, BK=16 (8 words), 256 threads (8 warps, 2x4), warp tile 64x32.
//    mma.sync.m16n8k16.bf16, fp32 accumulate. Double-buffered smem.
// ---------------------------------------------------------------------------
#define PAD 136

__device__ __forceinline__ void mma_bf16(float* c, const unsigned* a, const unsigned* b) {
    asm volatile(
        "mma.sync.aligned.m16n8k16.row.col.f32.bf16.bf16.f32 "
        "{%0,%1,%2,%3}, {%4,%5,%6,%7}, {%8,%9}, {%0,%1,%2,%3};"
        : "+f"(c[0]), "+f"(c[1]), "+f"(c[2]), "+f"(c[3])
        : "r"(a[0]), "r"(a[1]), "r"(a[2]), "r"(a[3]), "r"(b[0]), "r"(b[1]));
}

__global__ __launch_bounds__(256, 2) void gemm_bf16_bias_relu(
    const unsigned* __restrict__ A, const unsigned* __restrict__ Wp,
    const float* __restrict__ bias, unsigned* __restrict__ C,
    int M, int N, int KW)
{
    __shared__ unsigned As[2][8][PAD];  // [kpair][m]
    __shared__ unsigned Bs[2][8][PAD];  // [kpair][n]

    const int t = threadIdx.x;
    const int lane = t & 31;
    const int warp = t >> 5;
    const int wm = (warp >> 2) * 64;
    const int wn = (warp & 3) * 32;
    const int bm = blockIdx.y * 128;
    const int bn = blockIdx.x * 128;

    // global load mapping (uint4 each)
    const int am = t >> 1, aw = (t & 1) * 4;     // A: 128 rows x 8 words
    const int bw = t >> 5, bn4 = (t & 31) * 4;   // W: 8 kpairs x 128 n

    const unsigned* Ag = A + (size_t)(bm + am) * KW + aw;
    const unsigned* Wg = Wp + (size_t)bw * N + bn + bn4;

    float acc[4][4][4] = {};

    // prefetch stage 0
    uint4 ra = *(const uint4*)Ag;
    uint4 rw = *(const uint4*)Wg;
    As[0][aw + 0][am] = ra.x;
    As[0][aw + 1][am] = ra.y;
    As[0][aw + 2][am] = ra.z;
    As[0][aw + 3][am] = ra.w;
    *(uint4*)&Bs[0][bw][bn4] = rw;
    __syncthreads();

    const int nk = KW >> 3;
    const int r = lane >> 2, c = lane & 3;

    for (int k0 = 0; k0 < nk; k0++) {
        const int cur = k0 & 1;
        const bool more = (k0 + 1 < nk);
        if (more) {
            ra = *(const uint4*)(Ag + (k0 + 1) * 8);
            rw = *(const uint4*)(Wg + (size_t)(k0 + 1) * 8 * N);
        }

        unsigned a[4][4], b[4][2];
#pragma unroll
        for (int mt = 0; mt < 4; mt++) {
            int m = wm + mt * 16 + r;
            a[mt][0] = As[cur][c][m];
            a[mt][1] = As[cur][c][m + 8];
            a[mt][2] = As[cur][c + 4][m];
            a[mt][3] = As[cur][c + 4][m + 8];
        }
#pragma unroll
        for (int nt = 0; nt < 4; nt++) {
            int n = wn + nt * 8 + r;
            b[nt][0] = Bs[cur][c][n];
            b[nt][1] = Bs[cur][c + 4][n];
        }
#pragma unroll
        for (int mt = 0; mt < 4; mt++)
#pragma unroll
            for (int nt = 0; nt < 4; nt++)
                mma_bf16(acc[mt][nt], a[mt], b[nt]);

        if (more) {
            const int nxt = cur ^ 1;
            As[nxt][aw + 0][am] = ra.x;
            As[nxt][aw + 1][am] = ra.y;
            As[nxt][aw + 2][am] = ra.z;
            As[nxt][aw + 3][am] = ra.w;
            *(uint4*)&Bs[nxt][bw][bn4] = rw;
        }
        __syncthreads();
    }

    // epilogue: bias + relu, pack bf16x2 (consecutive n = consecutive k next layer)
    const int NW = N >> 1;
#pragma unroll
    for (int nt = 0; nt < 4; nt++) {
        int col = bn + wn + nt * 8 + 2 * c;
        float b0 = bias[col], b1 = bias[col + 1];
        int cw = col >> 1;
#pragma unroll
        for (int mt = 0; mt < 4; mt++) {
            int row0 = bm + wm + mt * 16 + r;
            unsigned o0 = pack_bf2(fmaxf(acc[mt][nt][0] + b0, 0.f),
                                   fmaxf(acc[mt][nt][1] + b1, 0.f));
            unsigned o1 = pack_bf2(fmaxf(acc[mt][nt][2] + b0, 0.f),
                                   fmaxf(acc[mt][nt][3] + b1, 0.f));
            C[(size_t)row0 * NW + cw] = o0;
            C[(size_t)(row0 + 8) * NW + cw] = o1;
        }
    }
}

// ---------------------------------------------------------------------------
// 5. output head: warp per sample. dot(h3, outW) + outB + li -> sigmoid
// ---------------------------------------------------------------------------
__global__ __launch_bounds__(256) void out_kernel(
    const float* __restrict__ outW, const float* __restrict__ outB,
    float* __restrict__ out, int B)
{
    int warp = (blockIdx.x * blockDim.x + threadIdx.x) >> 5;
    int lane = threadIdx.x & 31;
    if (warp >= B) return;
    const unsigned* h = g_h3 + (size_t)warp * NW3;
    float s = 0.f;
#pragma unroll
    for (int j = 0; j < NW3 / 32; j++) {
        unsigned w = h[lane + 32 * j];
        float2 hv = __bfloat1622float2(*(__nv_bfloat162*)&w);
        int k = 2 * (lane + 32 * j);
        s += hv.x * outW[k] + hv.y * outW[k + 1];
    }
#pragma unroll
    for (int o = 16; o; o >>= 1)
        s += __shfl_down_sync(0xffffffffu, s, o);
    if (lane == 0) {
        float x = s + outB[0] + g_li[warp];
        out[warp] = 1.f / (1.f + expf(-x));
    }
}

// ---------------------------------------------------------------------------
extern "C" void kernel_launch(void* const* d_in, const int* in_sizes, int n_in,
                              void* d_out, int out_size)
{
    const int*   feat_ids  = (const int*)  d_in[0];
    const float* feat_vals = (const float*)d_in[1];
    const float* FM_W      = (const float*)d_in[2];
    const float* FM_V      = (const float*)d_in[3];
    const float* FM_B      = (const float*)d_in[4];
    const float* emb       = (const float*)d_in[5];
    const float* W0        = (const float*)d_in[6];
    const float* B0        = (const float*)d_in[7];
    const float* W1        = (const float*)d_in[8];
    const float* B1        = (const float*)d_in[9];
    const float* W2        = (const float*)d_in[10];
    const float* B2        = (const float*)d_in[11];
    const float* outW      = (const float*)d_in[12];
    const float* outB      = (const float*)d_in[13];
    float* out = (float*)d_out;

    int B = in_sizes[0] / FIELD;
    if (B > MAXB) B = MAXB;

    unsigned *h0, *h1, *h2, *h3, *w0p, *w1p, *w2p;
    cudaGetSymbolAddress((void**)&h0, g_h0);
    cudaGetSymbolAddress((void**)&h1, g_h1);
    cudaGetSymbolAddress((void**)&h2, g_h2);
    cudaGetSymbolAddress((void**)&h3, g_h3);
    cudaGetSymbolAddress((void**)&w0p, g_w0p);
    cudaGetSymbolAddress((void**)&w1p, g_w1p);
    cudaGetSymbolAddress((void**)&w2p, g_w2p);

    compute_S_kernel<<<1, 256>>>(FM_V);
    pack_w_kernel<<<(KW0 * D1 + 255) / 256, 256>>>(W0, w0p, D0, D1, KW0);
    pack_w_kernel<<<(KW1 * D2 + 255) / 256, 256>>>(W1, w1p, D1, D2, KW1);
    pack_w_kernel<<<(KW2 * D3 + 255) / 256, 256>>>(W2, w2p, D2, D3, KW2);
    linear_inter_kernel<<<(B + 255) / 256, 256>>>(feat_ids, feat_vals, FM_W, FM_B, B);
    gather_kernel<<<(B * 40 + 255) / 256, 256>>>(feat_ids, emb, B);

    gemm_bf16_bias_relu<<<dim3(D1 / 128, B / 128), 256>>>(h0, w0p, B0, h1, B, D1, KW0);
    gemm_bf16_bias_relu<<<dim3(D2 / 128, B / 128), 256>>>(h1, w1p, B1, h2, B, D2, KW1);
    gemm_bf16_bias_relu<<<dim3(D3 / 128, B / 128), 256>>>(h2, w2p, B2, h3, B, D3, KW2);

    out_kernel<<<(B * 32 + 255) / 256, 256>>>(outW, outB, out, B);
}

// round 6
// speedup vs baseline: 4.2508x; 1.2357x over previous
#include <cuda_runtime.h>
#include <cuda_bf16.h>
#include <math.h>

#define FIELD 39
#define EMBD 8
#define MAXB 16384
#define D0 312
#define D0P 320
#define D1 512
#define D2 256
#define D3 128

#define KW0 (D0P / 2)    // 160 words per h0 row
#define KW1 (D1 / 2)     // 256
#define KW2 (D2 / 2)     // 128
#define NW3 (D3 / 2)     // 64

// Scratch (allocation-free rule). Activations packed bf16x2, k-contiguous.
__device__ float    g_li[MAXB];
__device__ unsigned g_h0[MAXB * KW0];
__device__ unsigned g_h1[MAXB * KW1];
__device__ unsigned g_h2[MAXB * KW2];
__device__ unsigned g_h3[MAXB * NW3];
// packed weights, layout [N][KW] (k-contiguous per output column)
__device__ unsigned g_w0p[D1 * KW0];
__device__ unsigned g_w1p[D2 * KW1];
__device__ unsigned g_w2p[D3 * KW2];

#define PACK_TOTAL (D1 * KW0 + D2 * KW1 + D3 * KW2)   // 163840

__device__ __forceinline__ unsigned pack_bf2(float a, float b) {
    __nv_bfloat162 p = __floats2bfloat162_rn(a, b);
    return *(unsigned*)&p;
}

// ---------------------------------------------------------------------------
// 1. fused prep kernel: block-range roles
//    [0, gB)            : embedding gather -> g_h0 (packed bf16, padded to 320)
//    [gB, gB+lB)        : linear + interaction (S recomputed per block)
//    [gB+lB, ...)       : pack all three weight matrices to [N][KW] bf16x2
// ---------------------------------------------------------------------------
__global__ __launch_bounds__(256) void prep_kernel(
    const int* __restrict__ ids, const float* __restrict__ vals,
    const float* __restrict__ FM_W, const float* __restrict__ FM_V,
    const float* __restrict__ FM_B, const float* __restrict__ emb,
    const float* __restrict__ W0, const float* __restrict__ W1,
    const float* __restrict__ W2, int B, int gB, int lB)
{
    const int bid = blockIdx.x;
    const int tid = threadIdx.x;

    if (bid < gB) {
        // ---- gather role ----
        int idx = bid * 256 + tid;
        if (idx >= B * 40) return;
        int b = idx / 40, f = idx % 40;
        uint4 o;
        if (f < FIELD) {
            int id = ids[b * FIELD + f];
            const float4* e = (const float4*)(emb + (size_t)id * EMBD);
            float4 e0 = e[0];
            float4 e1 = e[1];
            o.x = pack_bf2(e0.x, e0.y);
            o.y = pack_bf2(e0.z, e0.w);
            o.z = pack_bf2(e1.x, e1.y);
            o.w = pack_bf2(e1.z, e1.w);
        } else {
            o = make_uint4(0u, 0u, 0u, 0u);
        }
        *(uint4*)(g_h0 + (size_t)b * KW0 + f * 4) = o;
    } else if (bid < gB + lB) {
        // ---- linear + interaction role (S inline) ----
        __shared__ float Vi[FIELD][8][EMBD];
        __shared__ float Ss[FIELD * FIELD];
        for (int idx = tid; idx < FIELD * 64; idx += 256) {
            int i = idx / 64, r = idx % 64;
            long long off = (long long)i * (51000LL * 64LL) + r;
            Vi[i][r >> 3][r & 7] = FM_V[off];
        }
        __syncthreads();
        for (int idx = tid; idx < FIELD * FIELD; idx += 256) {
            int i = idx / FIELD, j = idx % FIELD;
            float s = 0.f;
            if (j > i) {
#pragma unroll
                for (int e = 0; e < EMBD; e++)
                    s += Vi[i][j & 7][e] * Vi[j][i & 7][e];
            }
            Ss[idx] = s;
        }
        __syncthreads();

        int b = (bid - gB) * 256 + tid;
        if (b >= B) return;
        float v[FIELD];
        float lin = 0.f;
#pragma unroll
        for (int f = 0; f < FIELD; f++) {
            v[f] = vals[b * FIELD + f];
            lin += FM_W[ids[b * FIELD + f]] * v[f];
        }
        float inter = 0.f;
#pragma unroll
        for (int i = 0; i < FIELD; i++) {
            float ti = 0.f;
#pragma unroll
            for (int j = i + 1; j < FIELD; j++)
                ti += Ss[i * FIELD + j] * v[j];
            inter += v[i] * ti;
        }
        g_li[b] = lin + inter + FM_B[0];
    } else {
        // ---- weight pack role: out[n*KW + kp] = bf16x2(W[2kp][n], W[2kp+1][n]) ----
        int p = (bid - gB - lB) * 256 + tid;
        if (p >= PACK_TOTAL) return;
        if (p < D1 * KW0) {
            int n = p / KW0, kp = p % KW0;
            int k = 2 * kp;
            float a = (k     < D0) ? W0[(size_t)k * D1 + n]       : 0.f;
            float c = (k + 1 < D0) ? W0[(size_t)(k + 1) * D1 + n] : 0.f;
            g_w0p[p] = pack_bf2(a, c);
        } else if (p < D1 * KW0 + D2 * KW1) {
            int q = p - D1 * KW0;
            int n = q / KW1, kp = q % KW1;
            int k = 2 * kp;
            g_w1p[q] = pack_bf2(W1[(size_t)k * D2 + n], W1[(size_t)(k + 1) * D2 + n]);
        } else {
            int q = p - D1 * KW0 - D2 * KW1;
            int n = q / KW2, kp = q % KW2;
            int k = 2 * kp;
            g_w2p[q] = pack_bf2(W2[(size_t)k * D3 + n], W2[(size_t)(k + 1) * D3 + n]);
        }
    }
}

// ---------------------------------------------------------------------------
// 2. bf16 GEMM + bias + ReLU: cp.async 3-stage pipeline + ldmatrix + swizzle.
//    A packed [M][KW], Wp packed [N][KW], C packed [M][N/2].
//    BM=BN=128, BK=32 elems (16 words), 8 warps (2x4), warp tile 64x32.
// ---------------------------------------------------------------------------
#define SSTG 3

__device__ __forceinline__ void ldmx4(unsigned &r0, unsigned &r1, unsigned &r2,
                                      unsigned &r3, unsigned addr) {
    asm volatile("ldmatrix.sync.aligned.m8n8.x4.shared.b16 {%0,%1,%2,%3}, [%4];"
                 : "=r"(r0), "=r"(r1), "=r"(r2), "=r"(r3) : "r"(addr));
}

__device__ __forceinline__ void mma_bf16(float* c, const unsigned* a, const unsigned* b) {
    asm volatile(
        "mma.sync.aligned.m16n8k16.row.col.f32.bf16.bf16.f32 "
        "{%0,%1,%2,%3}, {%4,%5,%6,%7}, {%8,%9}, {%0,%1,%2,%3};"
        : "+f"(c[0]), "+f"(c[1]), "+f"(c[2]), "+f"(c[3])
        : "r"(a[0]), "r"(a[1]), "r"(a[2]), "r"(a[3]), "r"(b[0]), "r"(b[1]));
}

__global__ __launch_bounds__(256, 2) void gemm_bf16_bias_relu(
    const unsigned* __restrict__ A, const unsigned* __restrict__ Wp,
    const float* __restrict__ bias, unsigned* __restrict__ C,
    int M, int N, int KW)
{
    // row = 64B (16 words), swizzled: phys_chunk = chunk ^ ((row>>1)&3)
    __shared__ unsigned As[SSTG][128 * 16];
    __shared__ unsigned Bs[SSTG][128 * 16];

    const int t = threadIdx.x;
    const int lane = t & 31;
    const int warp = t >> 5;
    const int wm = (warp >> 2) * 64;
    const int wn = (warp & 3) * 32;
    const int bm = blockIdx.y * 128;
    const int bn = blockIdx.x * 128;

    const unsigned aBase = (unsigned)__cvta_generic_to_shared(&As[0][0]);
    const unsigned bBase = (unsigned)__cvta_generic_to_shared(&Bs[0][0]);

    const int nk = KW >> 4;

    // per-thread cp.async mapping: 2 chunks (16B) each of A and B per stage
    auto load_stage = [&](int st, int kt) {
        int kw0 = kt * 16;
#pragma unroll
        for (int i = 0; i < 2; i++) {
            int idx = t + 256 * i;
            int m = idx >> 2, c = idx & 3;
            int pc = c ^ ((m >> 1) & 3);
            const unsigned* g = A + (size_t)(bm + m) * KW + kw0 + c * 4;
            unsigned s = aBase + st * 8192 + m * 64 + pc * 16;
            asm volatile("cp.async.cg.shared.global [%0], [%1], 16;" :: "r"(s), "l"(g));
        }
#pragma unroll
        for (int i = 0; i < 2; i++) {
            int idx = t + 256 * i;
            int n = idx >> 2, c = idx & 3;
            int pc = c ^ ((n >> 1) & 3);
            const unsigned* g = Wp + (size_t)(bn + n) * KW + kw0 + c * 4;
            unsigned s = bBase + st * 8192 + n * 64 + pc * 16;
            asm volatile("cp.async.cg.shared.global [%0], [%1], 16;" :: "r"(s), "l"(g));
        }
    };

    float acc[4][4][4] = {};

    // prologue: stages 0, 1
    load_stage(0, 0);
    asm volatile("cp.async.commit_group;" ::: "memory");
    if (nk > 1) load_stage(1, 1);
    asm volatile("cp.async.commit_group;" ::: "memory");

    const int r = lane >> 2, cc = lane & 3;
    const int lrow = lane & 15;          // ldmatrix row within 16
    const int lsel = lane >> 4;          // 0: k chunk lo, 1: k chunk hi

    for (int kt = 0; kt < nk; kt++) {
        asm volatile("cp.async.wait_group 1;" ::: "memory");
        __syncthreads();

        int pf = kt + SSTG - 1;
        if (pf < nk) load_stage(pf % SSTG, pf);
        asm volatile("cp.async.commit_group;" ::: "memory");

        unsigned aOff = aBase + (kt % SSTG) * 8192;
        unsigned bOff = bBase + (kt % SSTG) * 8192;

#pragma unroll
        for (int s = 0; s < 2; s++) {   // two k16 steps per BK=32
            unsigned a[4][4], b[4][2];
#pragma unroll
            for (int p = 0; p < 2; p++) {
                int n = wn + p * 16 + lrow;
                int lc = 2 * s + lsel;
                int pc = lc ^ ((n >> 1) & 3);
                unsigned r0, r1, r2, r3;
                ldmx4(r0, r1, r2, r3, bOff + n * 64 + pc * 16);
                b[2 * p][0] = r0;  b[2 * p + 1][0] = r1;
                b[2 * p][1] = r2;  b[2 * p + 1][1] = r3;
            }
#pragma unroll
            for (int mt = 0; mt < 4; mt++) {
                int m = wm + mt * 16 + lrow;
                int lc = 2 * s + lsel;
                int pc = lc ^ ((m >> 1) & 3);
                ldmx4(a[mt][0], a[mt][1], a[mt][2], a[mt][3], aOff + m * 64 + pc * 16);
            }
#pragma unroll
            for (int mt = 0; mt < 4; mt++)
#pragma unroll
                for (int nt = 0; nt < 4; nt++)
                    mma_bf16(acc[mt][nt], a[mt], b[nt]);
        }
    }

    // epilogue: bias + relu, pack bf16x2 (consecutive n -> next layer's k)
    const int NW = N >> 1;
#pragma unroll
    for (int nt = 0; nt < 4; nt++) {
        int col = bn + wn + nt * 8 + 2 * cc;
        float b0 = bias[col], b1 = bias[col + 1];
        int cw = col >> 1;
#pragma unroll
        for (int mt = 0; mt < 4; mt++) {
            int row0 = bm + wm + mt * 16 + r;
            unsigned o0 = pack_bf2(fmaxf(acc[mt][nt][0] + b0, 0.f),
                                   fmaxf(acc[mt][nt][1] + b1, 0.f));
            unsigned o1 = pack_bf2(fmaxf(acc[mt][nt][2] + b0, 0.f),
                                   fmaxf(acc[mt][nt][3] + b1, 0.f));
            C[(size_t)row0 * NW + cw] = o0;
            C[(size_t)(row0 + 8) * NW + cw] = o1;
        }
    }
}

// ---------------------------------------------------------------------------
// 3. output head: warp per sample. dot(h3, outW) + outB + li -> sigmoid
// ---------------------------------------------------------------------------
__global__ __launch_bounds__(256) void out_kernel(
    const float* __restrict__ outW, const float* __restrict__ outB,
    float* __restrict__ out, int B)
{
    int warp = (blockIdx.x * blockDim.x + threadIdx.x) >> 5;
    int lane = threadIdx.x & 31;
    if (warp >= B) return;
    const unsigned* h = g_h3 + (size_t)warp * NW3;
    float s = 0.f;
#pragma unroll
    for (int j = 0; j < NW3 / 32; j++) {
        unsigned w = h[lane + 32 * j];
        float2 hv = __bfloat1622float2(*(__nv_bfloat162*)&w);
        int k = 2 * (lane + 32 * j);
        s += hv.x * outW[k] + hv.y * outW[k + 1];
    }
#pragma unroll
    for (int o = 16; o; o >>= 1)
        s += __shfl_down_sync(0xffffffffu, s, o);
    if (lane == 0) {
        float x = s + outB[0] + g_li[warp];
        out[warp] = 1.f / (1.f + expf(-x));
    }
}

// ---------------------------------------------------------------------------
extern "C" void kernel_launch(void* const* d_in, const int* in_sizes, int n_in,
                              void* d_out, int out_size)
{
    const int*   feat_ids  = (const int*)  d_in[0];
    const float* feat_vals = (const float*)d_in[1];
    const float* FM_W      = (const float*)d_in[2];
    const float* FM_V      = (const float*)d_in[3];
    const float* FM_B      = (const float*)d_in[4];
    const float* emb       = (const float*)d_in[5];
    const float* W0        = (const float*)d_in[6];
    const float* B0        = (const float*)d_in[7];
    const float* W1        = (const float*)d_in[8];
    const float* B1        = (const float*)d_in[9];
    const float* W2        = (const float*)d_in[10];
    const float* B2        = (const float*)d_in[11];
    const float* outW      = (const float*)d_in[12];
    const float* outB      = (const float*)d_in[13];
    float* out = (float*)d_out;

    int B = in_sizes[0] / FIELD;
    if (B > MAXB) B = MAXB;

    unsigned *h0, *h1, *h2, *h3, *w0p, *w1p, *w2p;
    cudaGetSymbolAddress((void**)&h0, g_h0);
    cudaGetSymbolAddress((void**)&h1, g_h1);
    cudaGetSymbolAddress((void**)&h2, g_h2);
    cudaGetSymbolAddress((void**)&h3, g_h3);
    cudaGetSymbolAddress((void**)&w0p, g_w0p);
    cudaGetSymbolAddress((void**)&w1p, g_w1p);
    cudaGetSymbolAddress((void**)&w2p, g_w2p);

    int gB = (B * 40 + 255) / 256;
    int lB = (B + 255) / 256;
    int pB = (PACK_TOTAL + 255) / 256;

    prep_kernel<<<gB + lB + pB, 256>>>(feat_ids, feat_vals, FM_W, FM_V, FM_B, emb,
                                       W0, W1, W2, B, gB, lB);

    gemm_bf16_bias_relu<<<dim3(D1 / 128, B / 128), 256>>>(h0, w0p, B0, h1, B, D1, KW0);
    gemm_bf16_bias_relu<<<dim3(D2 / 128, B / 128), 256>>>(h1, w1p, B1, h2, B, D2, KW1);
    gemm_bf16_bias_relu<<<dim3(D3 / 128, B / 128), 256>>>(h2, w2p, B2, h3, B, D3, KW2);

    out_kernel<<<(B * 32 + 255) / 256, 256>>>(outW, outB, out, B);
}

// round 7
// speedup vs baseline: 4.4781x; 1.0535x over previous
#include <cuda_runtime.h>
#include <cuda_bf16.h>
#include <math.h>

#define FIELD 39
#define EMBD 8
#define MAXB 16384
#define D0 312
#define D0P 320
#define D1 512
#define D2 256
#define D3 128

#define KW0 (D0P / 2)    // 160 words per h0 row
#define KW1 (D1 / 2)     // 256
#define KW2 (D2 / 2)     // 128

// Scratch (allocation-free rule). Activations packed bf16x2, k-contiguous.
__device__ float    g_li[MAXB];
__device__ unsigned g_h0[MAXB * KW0];
__device__ unsigned g_h1[MAXB * KW1];
__device__ unsigned g_h2[MAXB * KW2];
// packed weights, layout [N][KW] (k-contiguous per output column)
__device__ unsigned g_w0p[D1 * KW0];
__device__ unsigned g_w1p[D2 * KW1];
__device__ unsigned g_w2p[D3 * KW2];

#define PACK_TOTAL (D1 * KW0 + D2 * KW1 + D3 * KW2)   // 163840

__device__ __forceinline__ unsigned pack_bf2(float a, float b) {
    __nv_bfloat162 p = __floats2bfloat162_rn(a, b);
    return *(unsigned*)&p;
}

// ---------------------------------------------------------------------------
// 1. fused prep kernel: block-range roles (gather | linear+inter | weight pack)
// ---------------------------------------------------------------------------
__global__ __launch_bounds__(256) void prep_kernel(
    const int* __restrict__ ids, const float* __restrict__ vals,
    const float* __restrict__ FM_W, const float* __restrict__ FM_V,
    const float* __restrict__ FM_B, const float* __restrict__ emb,
    const float* __restrict__ W0, const float* __restrict__ W1,
    const float* __restrict__ W2, int B, int gB, int lB)
{
    const int bid = blockIdx.x;
    const int tid = threadIdx.x;

    if (bid < gB) {
        int idx = bid * 256 + tid;
        if (idx >= B * 40) return;
        int b = idx / 40, f = idx % 40;
        uint4 o;
        if (f < FIELD) {
            int id = ids[b * FIELD + f];
            const float4* e = (const float4*)(emb + (size_t)id * EMBD);
            float4 e0 = e[0];
            float4 e1 = e[1];
            o.x = pack_bf2(e0.x, e0.y);
            o.y = pack_bf2(e0.z, e0.w);
            o.z = pack_bf2(e1.x, e1.y);
            o.w = pack_bf2(e1.z, e1.w);
        } else {
            o = make_uint4(0u, 0u, 0u, 0u);
        }
        *(uint4*)(g_h0 + (size_t)b * KW0 + f * 4) = o;
    } else if (bid < gB + lB) {
        __shared__ float Vi[FIELD][8][EMBD];
        __shared__ float Ss[FIELD * FIELD];
        for (int idx = tid; idx < FIELD * 64; idx += 256) {
            int i = idx / 64, r = idx % 64;
            long long off = (long long)i * (51000LL * 64LL) + r;
            Vi[i][r >> 3][r & 7] = FM_V[off];
        }
        __syncthreads();
        for (int idx = tid; idx < FIELD * FIELD; idx += 256) {
            int i = idx / FIELD, j = idx % FIELD;
            float s = 0.f;
            if (j > i) {
#pragma unroll
                for (int e = 0; e < EMBD; e++)
                    s += Vi[i][j & 7][e] * Vi[j][i & 7][e];
            }
            Ss[idx] = s;
        }
        __syncthreads();

        int b = (bid - gB) * 256 + tid;
        if (b >= B) return;
        float v[FIELD];
        float lin = 0.f;
#pragma unroll
        for (int f = 0; f < FIELD; f++) {
            v[f] = vals[b * FIELD + f];
            lin += FM_W[ids[b * FIELD + f]] * v[f];
        }
        float inter = 0.f;
#pragma unroll
        for (int i = 0; i < FIELD; i++) {
            float ti = 0.f;
#pragma unroll
            for (int j = i + 1; j < FIELD; j++)
                ti += Ss[i * FIELD + j] * v[j];
            inter += v[i] * ti;
        }
        g_li[b] = lin + inter + FM_B[0];
    } else {
        int p = (bid - gB - lB) * 256 + tid;
        if (p >= PACK_TOTAL) return;
        if (p < D1 * KW0) {
            int n = p / KW0, kp = p % KW0;
            int k = 2 * kp;
            float a = (k     < D0) ? W0[(size_t)k * D1 + n]       : 0.f;
            float c = (k + 1 < D0) ? W0[(size_t)(k + 1) * D1 + n] : 0.f;
            g_w0p[p] = pack_bf2(a, c);
        } else if (p < D1 * KW0 + D2 * KW1) {
            int q = p - D1 * KW0;
            int n = q / KW1, kp = q % KW1;
            int k = 2 * kp;
            g_w1p[q] = pack_bf2(W1[(size_t)k * D2 + n], W1[(size_t)(k + 1) * D2 + n]);
        } else {
            int q = p - D1 * KW0 - D2 * KW1;
            int n = q / KW2, kp = q % KW2;
            int k = 2 * kp;
            g_w2p[q] = pack_bf2(W2[(size_t)k * D3 + n], W2[(size_t)(k + 1) * D3 + n]);
        }
    }
}

// ---------------------------------------------------------------------------
// shared GEMM machinery: BM=64, BN=128, BK=32 elems (16 words), 8 warps,
// warp tile 32x32, 3-stage cp.async, swizzled smem, ldmatrix.x4.
// A packed [M][KW], Wp packed [N][KW].
// ---------------------------------------------------------------------------
#define SSTG 3
#define ASTG (64 * 16)    // words per A stage
#define BSTG (128 * 16)   // words per B stage

__device__ __forceinline__ void ldmx4(unsigned &r0, unsigned &r1, unsigned &r2,
                                      unsigned &r3, unsigned addr) {
    asm volatile("ldmatrix.sync.aligned.m8n8.x4.shared.b16 {%0,%1,%2,%3}, [%4];"
                 : "=r"(r0), "=r"(r1), "=r"(r2), "=r"(r3) : "r"(addr));
}

__device__ __forceinline__ void mma_bf16(float* c, const unsigned* a, const unsigned* b) {
    asm volatile(
        "mma.sync.aligned.m16n8k16.row.col.f32.bf16.bf16.f32 "
        "{%0,%1,%2,%3}, {%4,%5,%6,%7}, {%8,%9}, {%0,%1,%2,%3};"
        : "+f"(c[0]), "+f"(c[1]), "+f"(c[2]), "+f"(c[3])
        : "r"(a[0]), "r"(a[1]), "r"(a[2]), "r"(a[3]), "r"(b[0]), "r"(b[1]));
}

// mainloop macro body shared by both gemm kernels via inline function
struct Frag { float acc[2][4][4]; };

__device__ __forceinline__ void gemm_mainloop(
    const unsigned* __restrict__ A, const unsigned* __restrict__ Wp,
    int KW, int bm, int bn, unsigned* AsBase, unsigned* BsBase,
    int t, int lane, int wm, int wn, Frag &F)
{
    const unsigned aBase = (unsigned)__cvta_generic_to_shared(AsBase);
    const unsigned bBase = (unsigned)__cvta_generic_to_shared(BsBase);
    const int nk = KW >> 4;

    auto load_stage = [&](int st, int kt) {
        int kw0 = kt * 16;
        {
            int m = t >> 2, c = t & 3;
            int pc = c ^ ((m >> 1) & 3);
            const unsigned* g = A + (size_t)(bm + m) * KW + kw0 + c * 4;
            unsigned s = aBase + (st * ASTG + m * 16 + pc * 4) * 4;
            asm volatile("cp.async.cg.shared.global [%0], [%1], 16;" :: "r"(s), "l"(g));
        }
#pragma unroll
        for (int i = 0; i < 2; i++) {
            int idx = t + 256 * i;
            int n = idx >> 2, c = idx & 3;
            int pc = c ^ ((n >> 1) & 3);
            const unsigned* g = Wp + (size_t)(bn + n) * KW + kw0 + c * 4;
            unsigned s = bBase + (st * BSTG + n * 16 + pc * 4) * 4;
            asm volatile("cp.async.cg.shared.global [%0], [%1], 16;" :: "r"(s), "l"(g));
        }
    };

    load_stage(0, 0);
    asm volatile("cp.async.commit_group;" ::: "memory");
    if (nk > 1) load_stage(1, 1);
    asm volatile("cp.async.commit_group;" ::: "memory");

    const int lrow = lane & 15;
    const int lsel = lane >> 4;

    for (int kt = 0; kt < nk; kt++) {
        asm volatile("cp.async.wait_group 1;" ::: "memory");
        __syncthreads();

        int pf = kt + SSTG - 1;
        if (pf < nk) load_stage(pf % SSTG, pf);
        asm volatile("cp.async.commit_group;" ::: "memory");

        unsigned aOff = aBase + (kt % SSTG) * ASTG * 4;
        unsigned bOff = bBase + (kt % SSTG) * BSTG * 4;

#pragma unroll
        for (int s = 0; s < 2; s++) {
            unsigned a[2][4], b[4][2];
            int lc = 2 * s + lsel;
#pragma unroll
            for (int p = 0; p < 2; p++) {
                int n = wn + p * 16 + lrow;
                int pc = lc ^ ((n >> 1) & 3);
                unsigned r0, r1, r2, r3;
                ldmx4(r0, r1, r2, r3, bOff + (n * 16 + pc * 4) * 4);
                b[2 * p][0] = r0;  b[2 * p + 1][0] = r1;
                b[2 * p][1] = r2;  b[2 * p + 1][1] = r3;
            }
#pragma unroll
            for (int mt = 0; mt < 2; mt++) {
                int m = wm + mt * 16 + lrow;
                int pc = lc ^ ((m >> 1) & 3);
                ldmx4(a[mt][0], a[mt][1], a[mt][2], a[mt][3], aOff + (m * 16 + pc * 4) * 4);
            }
#pragma unroll
            for (int mt = 0; mt < 2; mt++)
#pragma unroll
                for (int nt = 0; nt < 4; nt++)
                    mma_bf16(F.acc[mt][nt], a[mt], b[nt]);
        }
    }
}

// ---------------------------------------------------------------------------
// 2. GEMM + bias + ReLU -> packed bf16x2 output
// ---------------------------------------------------------------------------
__global__ __launch_bounds__(256, 3) void gemm_bf16_bias_relu(
    const unsigned* __restrict__ A, const unsigned* __restrict__ Wp,
    const float* __restrict__ bias, unsigned* __restrict__ C,
    int N, int KW)
{
    __shared__ unsigned As[SSTG * ASTG];
    __shared__ unsigned Bs[SSTG * BSTG];

    const int t = threadIdx.x;
    const int lane = t & 31;
    const int warp = t >> 5;
    const int wm = (warp >> 2) * 32;
    const int wn = (warp & 3) * 32;
    const int bm = blockIdx.y * 64;
    const int bn = blockIdx.x * 128;

    Frag F = {};
    gemm_mainloop(A, Wp, KW, bm, bn, As, Bs, t, lane, wm, wn, F);

    const int r = lane >> 2, cc = lane & 3;
    const int NW = N >> 1;
#pragma unroll
    for (int nt = 0; nt < 4; nt++) {
        int col = bn + wn + nt * 8 + 2 * cc;
        float b0 = bias[col], b1 = bias[col + 1];
        int cw = col >> 1;
#pragma unroll
        for (int mt = 0; mt < 2; mt++) {
            int row0 = bm + wm + mt * 16 + r;
            unsigned o0 = pack_bf2(fmaxf(F.acc[mt][nt][0] + b0, 0.f),
                                   fmaxf(F.acc[mt][nt][1] + b1, 0.f));
            unsigned o1 = pack_bf2(fmaxf(F.acc[mt][nt][2] + b0, 0.f),
                                   fmaxf(F.acc[mt][nt][3] + b1, 0.f));
            C[(size_t)row0 * NW + cw] = o0;
            C[(size_t)(row0 + 8) * NW + cw] = o1;
        }
    }
}

// ---------------------------------------------------------------------------
// 3. last GEMM fused with output head: N = 128 = BN, so each CTA owns all
//    columns of its 64-row band. relu(acc+bias) dot outW, reduce, + li,
//    sigmoid -> out. No h3 materialization.
// ---------------------------------------------------------------------------
__global__ __launch_bounds__(256, 3) void gemm_last_head(
    const unsigned* __restrict__ A, const unsigned* __restrict__ Wp,
    const float* __restrict__ bias, const float* __restrict__ outW,
    const float* __restrict__ outB, float* __restrict__ out, int KW)
{
    __shared__ unsigned As[SSTG * ASTG];
    __shared__ unsigned Bs[SSTG * BSTG];
    __shared__ float red[64][4];

    const int t = threadIdx.x;
    const int lane = t & 31;
    const int warp = t >> 5;
    const int wm = (warp >> 2) * 32;
    const int wn = (warp & 3) * 32;
    const int bm = blockIdx.x * 64;

    Frag F = {};
    gemm_mainloop(A, Wp, KW, bm, 0, As, Bs, t, lane, wm, wn, F);

    const int r = lane >> 2, cc = lane & 3;
#pragma unroll
    for (int mt = 0; mt < 2; mt++) {
        float p0 = 0.f, p1 = 0.f;
#pragma unroll
        for (int nt = 0; nt < 4; nt++) {
            int col = wn + nt * 8 + 2 * cc;
            float b0 = bias[col], b1 = bias[col + 1];
            float w0 = outW[col], w1 = outW[col + 1];
            p0 += fmaxf(F.acc[mt][nt][0] + b0, 0.f) * w0
                + fmaxf(F.acc[mt][nt][1] + b1, 0.f) * w1;
            p1 += fmaxf(F.acc[mt][nt][2] + b0, 0.f) * w0
                + fmaxf(F.acc[mt][nt][3] + b1, 0.f) * w1;
        }
        // reduce over cc quad (lanes r*4 .. r*4+3)
        p0 += __shfl_xor_sync(0xffffffffu, p0, 1);
        p0 += __shfl_xor_sync(0xffffffffu, p0, 2);
        p1 += __shfl_xor_sync(0xffffffffu, p1, 1);
        p1 += __shfl_xor_sync(0xffffffffu, p1, 2);
        if (cc == 0) {
            red[wm + mt * 16 + r][warp & 3] = p0;
            red[wm + mt * 16 + r + 8][warp & 3] = p1;
        }
    }
    __syncthreads();
    if (t < 64) {
        float s = red[t][0] + red[t][1] + red[t][2] + red[t][3];
        float x = s + outB[0] + g_li[bm + t];
        out[bm + t] = 1.f / (1.f + expf(-x));
    }
}

// ---------------------------------------------------------------------------
extern "C" void kernel_launch(void* const* d_in, const int* in_sizes, int n_in,
                              void* d_out, int out_size)
{
    const int*   feat_ids  = (const int*)  d_in[0];
    const float* feat_vals = (const float*)d_in[1];
    const float* FM_W      = (const float*)d_in[2];
    const float* FM_V      = (const float*)d_in[3];
    const float* FM_B      = (const float*)d_in[4];
    const float* emb       = (const float*)d_in[5];
    const float* W0        = (const float*)d_in[6];
    const float* B0        = (const float*)d_in[7];
    const float* W1        = (const float*)d_in[8];
    const float* B1        = (const float*)d_in[9];
    const float* W2        = (const float*)d_in[10];
    const float* B2        = (const float*)d_in[11];
    const float* outW      = (const float*)d_in[12];
    const float* outB      = (const float*)d_in[13];
    float* out = (float*)d_out;

    int B = in_sizes[0] / FIELD;
    if (B > MAXB) B = MAXB;

    unsigned *h0, *h1, *h2, *w0p, *w1p, *w2p;
    cudaGetSymbolAddress((void**)&h0, g_h0);
    cudaGetSymbolAddress((void**)&h1, g_h1);
    cudaGetSymbolAddress((void**)&h2, g_h2);
    cudaGetSymbolAddress((void**)&w0p, g_w0p);
    cudaGetSymbolAddress((void**)&w1p, g_w1p);
    cudaGetSymbolAddress((void**)&w2p, g_w2p);

    int gB = (B * 40 + 255) / 256;
    int lB = (B + 255) / 256;
    int pB = (PACK_TOTAL + 255) / 256;

    prep_kernel<<<gB + lB + pB, 256>>>(feat_ids, feat_vals, FM_W, FM_V, FM_B, emb,
                                       W0, W1, W2, B, gB, lB);

    gemm_bf16_bias_relu<<<dim3(D1 / 128, B / 64), 256>>>(h0, w0p, B0, h1, D1, KW0);
    gemm_bf16_bias_relu<<<dim3(D2 / 128, B / 64), 256>>>(h1, w1p, B1, h2, D2, KW1);
    gemm_last_head<<<B / 64, 256>>>(h2, w2p, B2, outW, outB, out, KW2);
}